// round 5
// baseline (speedup 1.0000x reference)
#include <cuda_runtime.h>

#define BB 4
#define NN 512
#define DD 256

// ---------------- scratch (static device globals: allocation-free) ----------
__device__ float g_q[BB * NN * DD];     // 2 MB
__device__ float g_k[BB * NN * DD];     // 2 MB
__device__ float g_wei[BB * NN * NN];   // 4 MB

__device__ __forceinline__ float tanh_fast(float x) {
    float y;
    asm("tanh.approx.f32 %0, %1;" : "=f"(y) : "f"(x));
    return y;
}

// ---------------- kernel 1: q/k projections ---------------------------------
// C[n][e] = sum_d X[n][d] * W[e][d] + bias[e]   (x @ W^T + b)
// 64x64 tile, BK=16, 256 threads, 4x4 microtile.
__global__ __launch_bounds__(256) void proj_kernel(
    const float* __restrict__ X, const float* __restrict__ W,
    const float* __restrict__ bias, int which)
{
    float* out = which ? g_k : g_q;
    __shared__ float As[16][68];   // pad 68: <=2-way STS conflicts, 16B-aligned rows
    __shared__ float Bs[16][68];

    const int bn = blockIdx.x * 64;   // e tile
    const int bm = blockIdx.y * 64;   // token tile
    const int tid = threadIdx.x;
    const int tr = tid >> 4;          // 0..15
    const int tc = tid & 15;          // 0..15

    float acc[4][4] = {};

    for (int k0 = 0; k0 < DD; k0 += 16) {
        #pragma unroll
        for (int l = 0; l < 4; l++) {
            int idx = tid + 256 * l;          // 0..1023
            int i  = idx >> 4;
            int kk = idx & 15;
            As[kk][i] = X[(bm + i) * DD + k0 + kk];
            Bs[kk][i] = W[(bn + i) * DD + k0 + kk];
        }
        __syncthreads();
        #pragma unroll
        for (int kk = 0; kk < 16; kk++) {
            float a[4], b[4];
            #pragma unroll
            for (int u = 0; u < 4; u++) a[u] = As[kk][tr * 4 + u];
            #pragma unroll
            for (int v = 0; v < 4; v++) b[v] = Bs[kk][tc * 4 + v];
            #pragma unroll
            for (int u = 0; u < 4; u++)
                #pragma unroll
                for (int v = 0; v < 4; v++)
                    acc[u][v] = fmaf(a[u], b[v], acc[u][v]);
        }
        __syncthreads();
    }

    #pragma unroll
    for (int u = 0; u < 4; u++) {
        #pragma unroll
        for (int v = 0; v < 4; v++) {
            int e = bn + tc * 4 + v;
            out[(bm + tr * 4 + u) * DD + e] = acc[u][v] + bias[e];
        }
    }
}

// ---------------- kernel 2: additive-attention scores -----------------------
// wei[b,q,k] = sum_d Va[d] * tanh(q[b,q,d] + k[b,k,d])      (Va_b dropped:
// constant shift is softmax-invariant)
//
// Block: 256 thr (8 warps). Warp w owns k rows k0+4w..k0+4w+3.
// Lane = dg*4 + kis : dg = d-group (0..7, 32 d each), kis = k-sub (0..3).
// k-chunk (32 f) + V-chunk (32 f) live in registers; q staged in smem with
// padded layout off = d + 4*(d>>5) -> conflict-free, 16B-aligned LDS.128.
#define KT 32
#define QB 64
#define QSTAGE 32

__global__ __launch_bounds__(256, 2) void score_kernel(const float* __restrict__ Va)
{
    __shared__ __align__(16) float q_sh[QSTAGE][288];  // 36 floats per 32-d group

    const int tid  = threadIdx.x;
    const int w    = tid >> 5;
    const int lane = tid & 31;
    const int dg   = lane >> 2;     // 0..7
    const int kis  = lane & 3;      // 0..3

    const int b     = blockIdx.z;
    const int k0    = blockIdx.x * KT;
    const int qbase = blockIdx.y * QB;
    const int krow  = k0 + w * 4 + kis;

    float kreg[32], vreg[32];
    {
        const float4* kp = (const float4*)(g_k + ((b * NN + krow) << 8) + dg * 32);
        const float4* vp = (const float4*)(Va + dg * 32);
        #pragma unroll
        for (int j4 = 0; j4 < 8; j4++) {
            float4 kv = kp[j4];
            float4 vv = vp[j4];
            kreg[4*j4+0] = kv.x; kreg[4*j4+1] = kv.y; kreg[4*j4+2] = kv.z; kreg[4*j4+3] = kv.w;
            vreg[4*j4+0] = vv.x; vreg[4*j4+1] = vv.y; vreg[4*j4+2] = vv.z; vreg[4*j4+3] = vv.w;
        }
    }

    for (int qc = 0; qc < QB; qc += QSTAGE) {
        __syncthreads();
        // stage QSTAGE q rows (32*256 floats, 32 per thread)
        #pragma unroll 4
        for (int l = 0; l < (QSTAGE * DD) / 256; l++) {
            int idx = tid + 256 * l;
            int r = idx >> 8;
            int d = idx & 255;
            q_sh[r][d + ((d >> 5) << 2)] =
                g_q[((b * NN + qbase + qc + r) << 8) + d];
        }
        __syncthreads();

        for (int qi = 0; qi < QSTAGE; qi++) {
            const float4* q4 = (const float4*)(&q_sh[qi][dg * 36]);
            float a0 = 0.f, a1 = 0.f, a2 = 0.f, a3 = 0.f;
            #pragma unroll
            for (int j4 = 0; j4 < 8; j4++) {
                float4 qv = q4[j4];
                a0 = fmaf(vreg[4*j4+0], tanh_fast(qv.x + kreg[4*j4+0]), a0);
                a1 = fmaf(vreg[4*j4+1], tanh_fast(qv.y + kreg[4*j4+1]), a1);
                a2 = fmaf(vreg[4*j4+2], tanh_fast(qv.z + kreg[4*j4+2]), a2);
                a3 = fmaf(vreg[4*j4+3], tanh_fast(qv.w + kreg[4*j4+3]), a3);
            }
            float partial = (a0 + a1) + (a2 + a3);
            // reduce over dg (lane stride 4): xor 16, 8, 4
            partial += __shfl_xor_sync(0xffffffffu, partial, 16);
            partial += __shfl_xor_sync(0xffffffffu, partial, 8);
            partial += __shfl_xor_sync(0xffffffffu, partial, 4);
            if (dg == 0) {
                g_wei[((b * NN + qbase + qc + qi) << 9) + krow] = partial;
            }
        }
    }
}

// ---------------- kernel 3: masked softmax over k ----------------------------
__global__ __launch_bounds__(128) void softmax_kernel(const int* __restrict__ mask)
{
    const int row = blockIdx.x;               // b*N + q
    float* wrow = g_wei + row * NN;
    const int* mrow = mask + row * NN;
    const int t = threadIdx.x;
    __shared__ float red[4];

    float v[4];
    float mx = -1e30f;
    #pragma unroll
    for (int l = 0; l < 4; l++) {
        int k = t + 128 * l;
        float x = wrow[k];
        if (mrow[k] == 0) x = -1e30f;
        v[l] = x;
        mx = fmaxf(mx, x);
    }
    #pragma unroll
    for (int s = 16; s > 0; s >>= 1) mx = fmaxf(mx, __shfl_xor_sync(0xffffffffu, mx, s));
    if ((t & 31) == 0) red[t >> 5] = mx;
    __syncthreads();
    mx = fmaxf(fmaxf(red[0], red[1]), fmaxf(red[2], red[3]));

    float sum = 0.f;
    #pragma unroll
    for (int l = 0; l < 4; l++) {
        float e = __expf(v[l] - mx);
        v[l] = e;
        sum += e;
    }
    #pragma unroll
    for (int s = 16; s > 0; s >>= 1) sum += __shfl_xor_sync(0xffffffffu, sum, s);
    __syncthreads();
    if ((t & 31) == 0) red[t >> 5] = sum;
    __syncthreads();
    sum = red[0] + red[1] + red[2] + red[3];
    float inv = 1.0f / sum;
    #pragma unroll
    for (int l = 0; l < 4; l++) wrow[t + 128 * l] = v[l] * inv;
}

// ---------------- kernel 4: out = wei @ x ------------------------------------
// C[q][d] = sum_k wei[q][k] * x[k][d], per batch. Same 64x64x16 tiling.
__global__ __launch_bounds__(256) void av_kernel(const float* __restrict__ X,
                                                 float* __restrict__ out)
{
    __shared__ float As[16][68];
    __shared__ float Bs[16][68];

    const int b  = blockIdx.z;
    const int d0 = blockIdx.x * 64;
    const int q0 = blockIdx.y * 64;
    const float* A  = g_wei + b * NN * NN;   // [512][512]
    const float* Bm = X + b * NN * DD;       // [512][256]

    const int tid = threadIdx.x;
    const int tr = tid >> 4;
    const int tc = tid & 15;

    float acc[4][4] = {};

    for (int k0 = 0; k0 < NN; k0 += 16) {
        #pragma unroll
        for (int l = 0; l < 4; l++) {
            int idx = tid + 256 * l;
            int i  = idx >> 4;
            int kk = idx & 15;
            As[kk][i] = A[(q0 + i) * NN + k0 + kk];
            int kk2 = idx >> 6;       // 0..15
            int j   = idx & 63;       // 0..63
            Bs[kk2][j] = Bm[(k0 + kk2) * DD + d0 + j];
        }
        __syncthreads();
        #pragma unroll
        for (int kk = 0; kk < 16; kk++) {
            float a[4], bb[4];
            #pragma unroll
            for (int u = 0; u < 4; u++) a[u]  = As[kk][tr * 4 + u];
            #pragma unroll
            for (int v = 0; v < 4; v++) bb[v] = Bs[kk][tc * 4 + v];
            #pragma unroll
            for (int u = 0; u < 4; u++)
                #pragma unroll
                for (int v = 0; v < 4; v++)
                    acc[u][v] = fmaf(a[u], bb[v], acc[u][v]);
        }
        __syncthreads();
    }

    #pragma unroll
    for (int u = 0; u < 4; u++)
        #pragma unroll
        for (int v = 0; v < 4; v++)
            out[((b * NN + q0 + tr * 4 + u) << 8) + d0 + tc * 4 + v] = acc[u][v];
}

// ---------------- launcher ---------------------------------------------------
extern "C" void kernel_launch(void* const* d_in, const int* in_sizes, int n_in,
                              void* d_out, int out_size)
{
    const float* X    = (const float*)d_in[0];  // out  [4,512,256]
    const int*   mask = (const int*)  d_in[1];  // mask [4,512,512]
    const float* Wa_w = (const float*)d_in[2];  // [256,256]
    const float* Wa_b = (const float*)d_in[3];  // [256]
    const float* Ua_w = (const float*)d_in[4];  // [256,256]
    const float* Ua_b = (const float*)d_in[5];  // [256]
    const float* Va_w = (const float*)d_in[6];  // [1,256]
    // d_in[7] = Va_b : constant pre-softmax shift, softmax-invariant -> unused

    (void)in_sizes; (void)n_in; (void)out_size;

    dim3 pgrid(DD / 64, (BB * NN) / 64);        // 4 x 32
    proj_kernel<<<pgrid, 256>>>(X, Wa_w, Wa_b, 0);   // -> g_q
    proj_kernel<<<pgrid, 256>>>(X, Ua_w, Ua_b, 1);   // -> g_k

    dim3 sgrid(NN / KT, NN / QB, BB);           // 16 x 8 x 4 = 512 blocks
    score_kernel<<<sgrid, 256>>>(Va_w);

    softmax_kernel<<<BB * NN, 128>>>(mask);

    dim3 agrid(DD / 64, NN / 64, BB);           // 4 x 8 x 4
    av_kernel<<<agrid, 256>>>(X, (float*)d_out);
}

// round 7
// speedup vs baseline: 1.0733x; 1.0733x over previous
#include <cuda_runtime.h>
#include <cuda_fp16.h>

#define BB 4
#define NN 512
#define DD 256

// ---------------- scratch (static device globals: allocation-free) ----------
__device__ __align__(16) __half g_q[BB * NN * DD];    // 1 MB, fp16
__device__ __align__(16) __half g_k[BB * NN * DD];    // 1 MB, fp16
__device__ __align__(16) float  g_wei[BB * NN * NN];  // 4 MB

// NOTE: named tanh_h2 (not h2tanh) -- cuda_fp16.hpp defines h2tanh already.
__device__ __forceinline__ unsigned tanh_h2(unsigned xi) {
    unsigned yi;
    asm("tanh.approx.f16x2 %0, %1;" : "=r"(yi) : "r"(xi));
    return yi;
}

__device__ __forceinline__ unsigned hadd2_u(unsigned a, unsigned b) {
    unsigned c;
    asm("add.f16x2 %0, %1, %2;" : "=r"(c) : "r"(a), "r"(b));
    return c;
}

// ---------------- kernel 1: q/k projections (fused, fp16 output) ------------
// C[n][e] = sum_d X[n][d] * W[e][d] + bias[e]; blockIdx.z selects q/k side.
__global__ __launch_bounds__(256) void proj_kernel(
    const float* __restrict__ X,
    const float* __restrict__ Ww, const float* __restrict__ Wb,
    const float* __restrict__ Uw, const float* __restrict__ Ub)
{
    const float* W    = blockIdx.z ? Uw : Ww;
    const float* bias = blockIdx.z ? Ub : Wb;
    __half* out       = blockIdx.z ? g_k : g_q;

    __shared__ float As[16][68];
    __shared__ float Bs[16][68];

    const int bn = blockIdx.x * 64;   // e tile
    const int bm = blockIdx.y * 64;   // token tile
    const int tid = threadIdx.x;
    const int tr = tid >> 4;
    const int tc = tid & 15;

    const int e0 = bn + tc * 4;
    float bv[4];
    #pragma unroll
    for (int v = 0; v < 4; v++) bv[v] = bias[e0 + v];

    float acc[4][4] = {};

    for (int k0 = 0; k0 < DD; k0 += 16) {
        #pragma unroll
        for (int l = 0; l < 4; l++) {
            int idx = tid + 256 * l;
            int i  = idx >> 4;
            int kk = idx & 15;
            As[kk][i] = X[(bm + i) * DD + k0 + kk];
            Bs[kk][i] = W[(bn + i) * DD + k0 + kk];
        }
        __syncthreads();
        #pragma unroll
        for (int kk = 0; kk < 16; kk++) {
            float a[4], b[4];
            #pragma unroll
            for (int u = 0; u < 4; u++) a[u] = As[kk][tr * 4 + u];
            #pragma unroll
            for (int v = 0; v < 4; v++) b[v] = Bs[kk][tc * 4 + v];
            #pragma unroll
            for (int u = 0; u < 4; u++)
                #pragma unroll
                for (int v = 0; v < 4; v++)
                    acc[u][v] = fmaf(a[u], b[v], acc[u][v]);
        }
        __syncthreads();
    }

    #pragma unroll
    for (int u = 0; u < 4; u++) {
        __half2 h01 = __floats2half2_rn(acc[u][0] + bv[0], acc[u][1] + bv[1]);
        __half2 h23 = __floats2half2_rn(acc[u][2] + bv[2], acc[u][3] + bv[3]);
        __half2* op = reinterpret_cast<__half2*>(out + (bm + tr * 4 + u) * DD + e0);
        op[0] = h01;
        op[1] = h23;
    }
}

// ---------------- kernel 2: additive-attention scores (fp16x2 tanh) ---------
// wei[b,q,k] = sum_d Va[d] * tanh(q[b,q,d] + k[b,k,d])  (Va_b is a constant
// pre-softmax shift -> dropped).
//
// Lane = dg*4 + kis. Each thread owns 32 d (16 half2) of one k row (regs);
// q staged in smem as half2 with dg-group stride 40 half2 (80 B): the 8 dg
// LDS.128 addresses are distinct mod 128 B -> conflict-free, 16B-aligned.
#define KT 32
#define QB 64
#define QSTAGE 32

__global__ __launch_bounds__(256, 2) void score_kernel(const float* __restrict__ Va)
{
    __shared__ __align__(16) unsigned q_sh[QSTAGE][320];  // 8 groups * 40 half2

    const int tid  = threadIdx.x;
    const int w    = tid >> 5;
    const int lane = tid & 31;
    const int dg   = lane >> 2;     // 0..7  (32 d each)
    const int kis  = lane & 3;      // 0..3

    const int b     = blockIdx.z;
    const int k0    = blockIdx.x * KT;
    const int qbase = blockIdx.y * QB;
    const int krow  = k0 + w * 4 + kis;

    // k chunk: 16 half2 (as raw u32) in registers
    unsigned kreg[16];
    {
        const uint4* kp = reinterpret_cast<const uint4*>(
            g_k + ((b * NN + krow) << 8) + dg * 32);
        #pragma unroll
        for (int j = 0; j < 4; j++) {
            uint4 t = kp[j];
            kreg[4*j+0] = t.x; kreg[4*j+1] = t.y;
            kreg[4*j+2] = t.z; kreg[4*j+3] = t.w;
        }
    }
    // Va chunk: 32 fp32 in registers (accumulation stays fp32)
    float vreg[32];
    {
        const float4* vp = reinterpret_cast<const float4*>(Va + dg * 32);
        #pragma unroll
        for (int j = 0; j < 8; j++) {
            float4 v = vp[j];
            vreg[4*j+0] = v.x; vreg[4*j+1] = v.y; vreg[4*j+2] = v.z; vreg[4*j+3] = v.w;
        }
    }

    for (int qc = 0; qc < QB; qc += QSTAGE) {
        __syncthreads();
        // stage 32 q rows (4096 half2) via uint4: 4 iters/thread
        const uint4* gq4 = reinterpret_cast<const uint4*>(
            g_q + ((b * NN + qbase + qc) << 8));
        #pragma unroll
        for (int l = 0; l < 4; l++) {
            int idx = tid + 256 * l;          // 0..1023
            int r  = idx >> 5;                // row 0..31
            int p4 = idx & 31;                // uint4 index within row
            uint4 v = gq4[(r << 5) + p4];
            *reinterpret_cast<uint4*>(&q_sh[r][(p4 >> 2) * 40 + (p4 & 3) * 4]) = v;
        }
        __syncthreads();

        #pragma unroll 2
        for (int qi = 0; qi < QSTAGE; qi++) {
            const uint4* q4 = reinterpret_cast<const uint4*>(&q_sh[qi][dg * 40]);
            float a0 = 0.f, a1 = 0.f, a2 = 0.f, a3 = 0.f;
            #pragma unroll
            for (int j = 0; j < 4; j++) {
                uint4 qv = q4[j];
                unsigned qh[4] = {qv.x, qv.y, qv.z, qv.w};
                #pragma unroll
                for (int u = 0; u < 4; u++) {
                    int i = 4 * j + u;
                    unsigned t = tanh_h2(hadd2_u(qh[u], kreg[i]));
                    __half2 th = *reinterpret_cast<__half2*>(&t);
                    float2 f = __half22float2(th);
                    if (u & 1) {
                        a2 = fmaf(vreg[2*i],   f.x, a2);
                        a3 = fmaf(vreg[2*i+1], f.y, a3);
                    } else {
                        a0 = fmaf(vreg[2*i],   f.x, a0);
                        a1 = fmaf(vreg[2*i+1], f.y, a1);
                    }
                }
            }
            float partial = (a0 + a1) + (a2 + a3);
            // reduce over dg (lane stride 4)
            partial += __shfl_xor_sync(0xffffffffu, partial, 16);
            partial += __shfl_xor_sync(0xffffffffu, partial, 8);
            partial += __shfl_xor_sync(0xffffffffu, partial, 4);
            if (dg == 0) {
                g_wei[((b * NN + qbase + qc + qi) << 9) + krow] = partial;
            }
        }
    }
}

// ---------------- kernel 3: masked softmax (vectorized) ----------------------
__global__ __launch_bounds__(128) void softmax_kernel(const int* __restrict__ mask)
{
    const int row = blockIdx.x;               // b*N + q
    float* wrow = g_wei + row * NN;
    const int* mrow = mask + row * NN;
    const int t = threadIdx.x;
    __shared__ float red[4];

    float4 v = reinterpret_cast<const float4*>(wrow)[t];
    int4   m = reinterpret_cast<const int4*>(mrow)[t];
    if (m.x == 0) v.x = -1e30f;
    if (m.y == 0) v.y = -1e30f;
    if (m.z == 0) v.z = -1e30f;
    if (m.w == 0) v.w = -1e30f;

    float mx = fmaxf(fmaxf(v.x, v.y), fmaxf(v.z, v.w));
    #pragma unroll
    for (int s = 16; s > 0; s >>= 1) mx = fmaxf(mx, __shfl_xor_sync(0xffffffffu, mx, s));
    if ((t & 31) == 0) red[t >> 5] = mx;
    __syncthreads();
    mx = fmaxf(fmaxf(red[0], red[1]), fmaxf(red[2], red[3]));
    __syncthreads();

    v.x = __expf(v.x - mx); v.y = __expf(v.y - mx);
    v.z = __expf(v.z - mx); v.w = __expf(v.w - mx);
    float sum = (v.x + v.y) + (v.z + v.w);
    #pragma unroll
    for (int s = 16; s > 0; s >>= 1) sum += __shfl_xor_sync(0xffffffffu, sum, s);
    if ((t & 31) == 0) red[t >> 5] = sum;
    __syncthreads();
    sum = (red[0] + red[1]) + (red[2] + red[3]);
    float inv = 1.0f / sum;
    v.x *= inv; v.y *= inv; v.z *= inv; v.w *= inv;
    reinterpret_cast<float4*>(wrow)[t] = v;
}

// ---------------- kernel 4: out = wei @ x ------------------------------------
__global__ __launch_bounds__(256) void av_kernel(const float* __restrict__ X,
                                                 float* __restrict__ out)
{
    __shared__ float As[16][68];
    __shared__ float Bs[16][68];

    const int b  = blockIdx.z;
    const int d0 = blockIdx.x * 64;
    const int q0 = blockIdx.y * 64;
    const float* A  = g_wei + b * NN * NN;   // [512][512]
    const float* Bm = X + b * NN * DD;       // [512][256]

    const int tid = threadIdx.x;
    const int tr = tid >> 4;
    const int tc = tid & 15;

    float acc[4][4] = {};

    for (int k0 = 0; k0 < NN; k0 += 16) {
        #pragma unroll
        for (int l = 0; l < 4; l++) {
            int idx = tid + 256 * l;
            int i  = idx >> 4;
            int kk = idx & 15;
            As[kk][i] = A[(q0 + i) * NN + k0 + kk];
            int kk2 = idx >> 6;
            int j   = idx & 63;
            Bs[kk2][j] = Bm[(k0 + kk2) * DD + d0 + j];
        }
        __syncthreads();
        #pragma unroll
        for (int kk = 0; kk < 16; kk++) {
            float a[4], bb[4];
            #pragma unroll
            for (int u = 0; u < 4; u++) a[u]  = As[kk][tr * 4 + u];
            #pragma unroll
            for (int v = 0; v < 4; v++) bb[v] = Bs[kk][tc * 4 + v];
            #pragma unroll
            for (int u = 0; u < 4; u++)
                #pragma unroll
                for (int v = 0; v < 4; v++)
                    acc[u][v] = fmaf(a[u], bb[v], acc[u][v]);
        }
        __syncthreads();
    }

    #pragma unroll
    for (int u = 0; u < 4; u++)
        #pragma unroll
        for (int v = 0; v < 4; v++)
            out[((b * NN + q0 + tr * 4 + u) << 8) + d0 + tc * 4 + v] = acc[u][v];
}

// ---------------- launcher ---------------------------------------------------
extern "C" void kernel_launch(void* const* d_in, const int* in_sizes, int n_in,
                              void* d_out, int out_size)
{
    const float* X    = (const float*)d_in[0];  // out  [4,512,256]
    const int*   mask = (const int*)  d_in[1];  // mask [4,512,512]
    const float* Wa_w = (const float*)d_in[2];  // [256,256]
    const float* Wa_b = (const float*)d_in[3];  // [256]
    const float* Ua_w = (const float*)d_in[4];  // [256,256]
    const float* Ua_b = (const float*)d_in[5];  // [256]
    const float* Va_w = (const float*)d_in[6];  // [1,256]
    // d_in[7] = Va_b : softmax-invariant constant -> unused

    (void)in_sizes; (void)n_in; (void)out_size;

    dim3 pgrid(DD / 64, (BB * NN) / 64, 2);     // 4 x 32 x 2 = 256 blocks
    proj_kernel<<<pgrid, 256>>>(X, Wa_w, Wa_b, Ua_w, Ua_b);

    dim3 sgrid(NN / KT, NN / QB, BB);           // 16 x 8 x 4 = 512 blocks
    score_kernel<<<sgrid, 256>>>(Va_w);

    softmax_kernel<<<BB * NN, 128>>>(mask);

    dim3 agrid(DD / 64, NN / 64, BB);           // 4 x 8 x 4
    av_kernel<<<agrid, 256>>>(X, (float*)d_out);
}

// round 9
// speedup vs baseline: 1.4595x; 1.3599x over previous
#include <cuda_runtime.h>
#include <cuda_fp16.h>

#define BB 4
#define NN 512
#define DD 256

// ---------------- scratch (static device globals: allocation-free) ----------
__device__ __align__(16) __half g_q[BB * NN * DD];     // 1 MB
__device__ __align__(16) __half g_k[BB * NN * DD];     // 1 MB
__device__ __align__(16) float  g_wei[BB * NN * NN];   // 4 MB (raw scores)
__device__ __align__(16) __half g_weih[BB * NN * NN];  // 2 MB (softmaxed, fp16)
__device__ __align__(16) __half g_xh[BB * NN * DD];    // 1 MB (X in fp16)
__device__ __align__(16) __half g_wh[DD * DD];         // Wa_w fp16
__device__ __align__(16) __half g_uh[DD * DD];         // Ua_w fp16

// ---------------- small PTX helpers ------------------------------------------
__device__ __forceinline__ unsigned tanh_h2(unsigned xi) {
    unsigned yi;
    asm("tanh.approx.f16x2 %0, %1;" : "=r"(yi) : "r"(xi));
    return yi;
}
__device__ __forceinline__ unsigned hadd2_u(unsigned a, unsigned b) {
    unsigned c;
    asm("add.f16x2 %0, %1, %2;" : "=r"(c) : "r"(a), "r"(b));
    return c;
}
__device__ __forceinline__ unsigned smem_u32(const void* p) {
    return (unsigned)__cvta_generic_to_shared(p);
}
__device__ __forceinline__ void ldsm_x4(unsigned* r, const __half* p) {
    unsigned a = smem_u32(p);
    asm volatile("ldmatrix.sync.aligned.m8n8.x4.shared.b16 {%0,%1,%2,%3}, [%4];"
        : "=r"(r[0]), "=r"(r[1]), "=r"(r[2]), "=r"(r[3]) : "r"(a));
}
__device__ __forceinline__ void ldsm_x4_trans(unsigned* r, const __half* p) {
    unsigned a = smem_u32(p);
    asm volatile("ldmatrix.sync.aligned.m8n8.x4.trans.shared.b16 {%0,%1,%2,%3}, [%4];"
        : "=r"(r[0]), "=r"(r[1]), "=r"(r[2]), "=r"(r[3]) : "r"(a));
}
__device__ __forceinline__ void mma16816(float* c, const unsigned* a,
                                         unsigned b0, unsigned b1) {
    asm volatile("mma.sync.aligned.m16n8k16.row.col.f32.f16.f16.f32 "
        "{%0,%1,%2,%3}, {%4,%5,%6,%7}, {%8,%9}, {%0,%1,%2,%3};"
        : "+f"(c[0]), "+f"(c[1]), "+f"(c[2]), "+f"(c[3])
        : "r"(a[0]), "r"(a[1]), "r"(a[2]), "r"(a[3]), "r"(b0), "r"(b1));
}

// ---------------- kernel 0: fp32 -> fp16 conversions --------------------------
// Counts are in float4 units:
//   X    = 524288 floats = 131072 f4
//   Wa_w =  65536 floats =  16384 f4   -> cumulative 147456
//   Ua_w =  65536 floats =  16384 f4   -> cumulative 163840
__global__ __launch_bounds__(256) void conv_kernel(
    const float4* __restrict__ X4, const float4* __restrict__ Wa4,
    const float4* __restrict__ Ua4)
{
    int i = blockIdx.x * 256 + threadIdx.x;     // 0 .. 163839
    const float4* src;
    uint2* dst;
    int j;
    if (i < 131072)      { src = X4;  j = i;          dst = (uint2*)g_xh; }
    else if (i < 147456) { src = Wa4; j = i - 131072; dst = (uint2*)g_wh; }
    else                 { src = Ua4; j = i - 147456; dst = (uint2*)g_uh; }
    float4 v = src[j];
    __half2 h01 = __floats2half2_rn(v.x, v.y);
    __half2 h23 = __floats2half2_rn(v.z, v.w);
    uint2 o;
    o.x = *reinterpret_cast<unsigned*>(&h01);
    o.y = *reinterpret_cast<unsigned*>(&h23);
    dst[j] = o;
}

// ---------------- kernel 1: q/k projections via HMMA -------------------------
// out[n][e] = sum_d Xh[n][d] * Wh[e][d] + bias[e], fp16 out. BM=128 BN=64 BK=32.
// blockIdx.z selects q/k side. grid (4, 16, 2), 256 thr (8 warps, 4x2).
__global__ __launch_bounds__(256) void proj_mma(
    const float* __restrict__ Wb, const float* __restrict__ Ub)
{
    __shared__ __half As[128][40];   // 80B row stride: ldmatrix conflict-free
    __shared__ __half Bs[64][40];

    const __half* A    = g_xh;
    const __half* Bw   = blockIdx.z ? g_uh : g_wh;
    const float*  bias = blockIdx.z ? Ub : Wb;
    __half*       out  = blockIdx.z ? g_k : g_q;

    const int bn = blockIdx.x * 64;
    const int bm = blockIdx.y * 128;
    const int tid = threadIdx.x, warp = tid >> 5, lane = tid & 31;
    const int wm = warp >> 1, wn = warp & 1;   // warp tile 32x32
    const int gq = lane >> 2, tq = lane & 3;

    float acc[2][4][4] = {};   // [tm16][tn8][4]

    for (int k0 = 0; k0 < DD; k0 += 32) {
        __syncthreads();
        #pragma unroll
        for (int l = 0; l < 2; l++) {
            int idx = tid + 256 * l;
            int row = idx >> 2, q4 = idx & 3;
            *(uint4*)&As[row][q4 * 8] =
                *(const uint4*)&A[(bm + row) * DD + k0 + q4 * 8];
        }
        {
            int row = tid >> 2, q4 = tid & 3;
            *(uint4*)&Bs[row][q4 * 8] =
                *(const uint4*)&Bw[(bn + row) * DD + k0 + q4 * 8];
        }
        __syncthreads();

        #pragma unroll
        for (int ks = 0; ks < 2; ks++) {
            int kc = ks * 16;
            unsigned a[2][4], bf[2][4];
            #pragma unroll
            for (int tm = 0; tm < 2; tm++) {
                int r = wm * 32 + tm * 16 + (lane & 15);
                int c = kc + 8 * (lane >> 4);
                ldsm_x4(a[tm], &As[r][c]);
            }
            #pragma unroll
            for (int tn = 0; tn < 2; tn++) {
                int r = wn * 32 + tn * 16 + (lane & 7) + 8 * (lane >> 4);
                int c = kc + 8 * ((lane >> 3) & 1);
                ldsm_x4(bf[tn], &Bs[r][c]);
            }
            #pragma unroll
            for (int tm = 0; tm < 2; tm++)
                #pragma unroll
                for (int tn8 = 0; tn8 < 4; tn8++)
                    mma16816(acc[tm][tn8], a[tm],
                             bf[tn8 >> 1][(tn8 & 1) * 2],
                             bf[tn8 >> 1][(tn8 & 1) * 2 + 1]);
        }
    }

    #pragma unroll
    for (int tm = 0; tm < 2; tm++) {
        #pragma unroll
        for (int tn8 = 0; tn8 < 4; tn8++) {
            int c = bn + wn * 32 + tn8 * 8 + 2 * tq;
            float2 bv = *(const float2*)&bias[c];
            int r0 = bm + wm * 32 + tm * 16 + gq;
            __half2 h0 = __floats2half2_rn(acc[tm][tn8][0] + bv.x,
                                           acc[tm][tn8][1] + bv.y);
            __half2 h1 = __floats2half2_rn(acc[tm][tn8][2] + bv.x,
                                           acc[tm][tn8][3] + bv.y);
            *(__half2*)&out[r0 * DD + c] = h0;
            *(__half2*)&out[(r0 + 8) * DD + c] = h1;
        }
    }
}

// ---------------- kernel 2: additive-attention scores (fp16x2 tanh) ---------
#define KT 32
#define QB 64
#define QSTAGE 32

__global__ __launch_bounds__(256, 2) void score_kernel(const float* __restrict__ Va)
{
    __shared__ __align__(16) unsigned q_sh[QSTAGE][320];

    const int tid  = threadIdx.x;
    const int w    = tid >> 5;
    const int lane = tid & 31;
    const int dg   = lane >> 2;
    const int kis  = lane & 3;

    const int b     = blockIdx.z;
    const int k0    = blockIdx.x * KT;
    const int qbase = blockIdx.y * QB;
    const int krow  = k0 + w * 4 + kis;

    unsigned kreg[16];
    {
        const uint4* kp = reinterpret_cast<const uint4*>(
            g_k + ((b * NN + krow) << 8) + dg * 32);
        #pragma unroll
        for (int j = 0; j < 4; j++) {
            uint4 t = kp[j];
            kreg[4*j+0] = t.x; kreg[4*j+1] = t.y;
            kreg[4*j+2] = t.z; kreg[4*j+3] = t.w;
        }
    }
    float vreg[32];
    {
        const float4* vp = reinterpret_cast<const float4*>(Va + dg * 32);
        #pragma unroll
        for (int j = 0; j < 8; j++) {
            float4 v = vp[j];
            vreg[4*j+0] = v.x; vreg[4*j+1] = v.y; vreg[4*j+2] = v.z; vreg[4*j+3] = v.w;
        }
    }

    for (int qc = 0; qc < QB; qc += QSTAGE) {
        __syncthreads();
        const uint4* gq4 = reinterpret_cast<const uint4*>(
            g_q + ((b * NN + qbase + qc) << 8));
        #pragma unroll
        for (int l = 0; l < 4; l++) {
            int idx = tid + 256 * l;
            int r  = idx >> 5;
            int p4 = idx & 31;
            uint4 v = gq4[(r << 5) + p4];
            *reinterpret_cast<uint4*>(&q_sh[r][(p4 >> 2) * 40 + (p4 & 3) * 4]) = v;
        }
        __syncthreads();

        #pragma unroll 2
        for (int qi = 0; qi < QSTAGE; qi++) {
            const uint4* q4 = reinterpret_cast<const uint4*>(&q_sh[qi][dg * 40]);
            float a0 = 0.f, a1 = 0.f, a2 = 0.f, a3 = 0.f;
            #pragma unroll
            for (int j = 0; j < 4; j++) {
                uint4 qv = q4[j];
                unsigned qh[4] = {qv.x, qv.y, qv.z, qv.w};
                #pragma unroll
                for (int u = 0; u < 4; u++) {
                    int i = 4 * j + u;
                    unsigned t = tanh_h2(hadd2_u(qh[u], kreg[i]));
                    __half2 th = *reinterpret_cast<__half2*>(&t);
                    float2 f = __half22float2(th);
                    if (u & 1) {
                        a2 = fmaf(vreg[2*i],   f.x, a2);
                        a3 = fmaf(vreg[2*i+1], f.y, a3);
                    } else {
                        a0 = fmaf(vreg[2*i],   f.x, a0);
                        a1 = fmaf(vreg[2*i+1], f.y, a1);
                    }
                }
            }
            float partial = (a0 + a1) + (a2 + a3);
            partial += __shfl_xor_sync(0xffffffffu, partial, 16);
            partial += __shfl_xor_sync(0xffffffffu, partial, 8);
            partial += __shfl_xor_sync(0xffffffffu, partial, 4);
            if (dg == 0) {
                g_wei[((b * NN + qbase + qc + qi) << 9) + krow] = partial;
            }
        }
    }
}

// ---------------- kernel 3: masked softmax -> fp16 weights -------------------
__global__ __launch_bounds__(128) void softmax_kernel(const int* __restrict__ mask)
{
    const int row = blockIdx.x;
    const float* wrow = g_wei + row * NN;
    const int* mrow = mask + row * NN;
    const int t = threadIdx.x;
    __shared__ float red[4];

    float4 v = reinterpret_cast<const float4*>(wrow)[t];
    int4   m = reinterpret_cast<const int4*>(mrow)[t];
    if (m.x == 0) v.x = -1e30f;
    if (m.y == 0) v.y = -1e30f;
    if (m.z == 0) v.z = -1e30f;
    if (m.w == 0) v.w = -1e30f;

    float mx = fmaxf(fmaxf(v.x, v.y), fmaxf(v.z, v.w));
    #pragma unroll
    for (int s = 16; s > 0; s >>= 1) mx = fmaxf(mx, __shfl_xor_sync(0xffffffffu, mx, s));
    if ((t & 31) == 0) red[t >> 5] = mx;
    __syncthreads();
    mx = fmaxf(fmaxf(red[0], red[1]), fmaxf(red[2], red[3]));
    __syncthreads();

    v.x = __expf(v.x - mx); v.y = __expf(v.y - mx);
    v.z = __expf(v.z - mx); v.w = __expf(v.w - mx);
    float sum = (v.x + v.y) + (v.z + v.w);
    #pragma unroll
    for (int s = 16; s > 0; s >>= 1) sum += __shfl_xor_sync(0xffffffffu, sum, s);
    if ((t & 31) == 0) red[t >> 5] = sum;
    __syncthreads();
    sum = (red[0] + red[1]) + (red[2] + red[3]);
    float inv = 1.0f / sum;

    __half2 h01 = __floats2half2_rn(v.x * inv, v.y * inv);
    __half2 h23 = __floats2half2_rn(v.z * inv, v.w * inv);
    uint2 o;
    o.x = *reinterpret_cast<unsigned*>(&h01);
    o.y = *reinterpret_cast<unsigned*>(&h23);
    reinterpret_cast<uint2*>(g_weih + row * NN)[t] = o;
}

// ---------------- kernel 4: out = wei @ X via HMMA ---------------------------
// C[q][d] = sum_k weih[q][k] * Xh[k][d], per batch. BM=64 BN=64 BK=32.
// grid (4, 8, 4), 256 thr (8 warps as 2x4; warp tile 32x16).
__global__ __launch_bounds__(256) void av_mma(float* __restrict__ out)
{
    __shared__ __half As[64][40];
    __shared__ __half Bs[32][72];   // 144B row stride: conflict-free trans

    const int b  = blockIdx.z;
    const int bn = blockIdx.x * 64;   // d
    const int bm = blockIdx.y * 64;   // q
    const __half* A  = g_weih + b * NN * NN;
    const __half* Bx = g_xh + b * NN * DD;

    const int tid = threadIdx.x, warp = tid >> 5, lane = tid & 31;
    const int wm = warp >> 2, wn = warp & 3;   // warp tile 32x16
    const int gq = lane >> 2, tq = lane & 3;

    float acc[2][2][4] = {};

    for (int k0 = 0; k0 < NN; k0 += 32) {
        __syncthreads();
        {
            int row = tid >> 2, q4 = tid & 3;
            *(uint4*)&As[row][q4 * 8] =
                *(const uint4*)&A[(bm + row) * NN + k0 + q4 * 8];
        }
        {
            int row = tid >> 3, q8 = tid & 7;
            *(uint4*)&Bs[row][q8 * 8] =
                *(const uint4*)&Bx[(k0 + row) * DD + bn + q8 * 8];
        }
        __syncthreads();

        #pragma unroll
        for (int ks = 0; ks < 2; ks++) {
            int kc = ks * 16;
            unsigned a[2][4], bf[4];
            #pragma unroll
            for (int tm = 0; tm < 2; tm++) {
                int r = wm * 32 + tm * 16 + (lane & 15);
                int c = kc + 8 * (lane >> 4);
                ldsm_x4(a[tm], &As[r][c]);
            }
            {
                int kr = kc + (lane & 7) + 8 * ((lane >> 3) & 1);
                int nc = wn * 16 + 8 * (lane >> 4);
                ldsm_x4_trans(bf, &Bs[kr][nc]);
            }
            #pragma unroll
            for (int tm = 0; tm < 2; tm++)
                #pragma unroll
                for (int tn8 = 0; tn8 < 2; tn8++)
                    mma16816(acc[tm][tn8], a[tm], bf[tn8 * 2], bf[tn8 * 2 + 1]);
        }
    }

    #pragma unroll
    for (int tm = 0; tm < 2; tm++) {
        #pragma unroll
        for (int tn8 = 0; tn8 < 2; tn8++) {
            int c  = bn + wn * 16 + tn8 * 8 + 2 * tq;
            int r0 = bm + wm * 32 + tm * 16 + gq;
            *(float2*)&out[(b * NN + r0) * DD + c] =
                make_float2(acc[tm][tn8][0], acc[tm][tn8][1]);
            *(float2*)&out[(b * NN + r0 + 8) * DD + c] =
                make_float2(acc[tm][tn8][2], acc[tm][tn8][3]);
        }
    }
}

// ---------------- launcher ---------------------------------------------------
extern "C" void kernel_launch(void* const* d_in, const int* in_sizes, int n_in,
                              void* d_out, int out_size)
{
    const float* X    = (const float*)d_in[0];  // [4,512,256]
    const int*   mask = (const int*)  d_in[1];  // [4,512,512]
    const float* Wa_w = (const float*)d_in[2];  // [256,256]
    const float* Wa_b = (const float*)d_in[3];  // [256]
    const float* Ua_w = (const float*)d_in[4];  // [256,256]
    const float* Ua_b = (const float*)d_in[5];  // [256]
    const float* Va_w = (const float*)d_in[6];  // [1,256]
    // d_in[7] = Va_b : softmax-invariant constant -> unused

    (void)in_sizes; (void)n_in; (void)out_size;

    conv_kernel<<<640, 256>>>((const float4*)X, (const float4*)Wa_w,
                              (const float4*)Ua_w);

    dim3 pgrid(DD / 64, (BB * NN) / 128, 2);    // 4 x 16 x 2 = 128 blocks
    proj_mma<<<pgrid, 256>>>(Wa_b, Ua_b);

    dim3 sgrid(NN / KT, NN / QB, BB);           // 16 x 8 x 4 = 512 blocks
    score_kernel<<<sgrid, 256>>>(Va_w);

    softmax_kernel<<<BB * NN, 128>>>(mask);

    dim3 agrid(DD / 64, NN / 64, BB);           // 4 x 8 x 4 = 128 blocks
    av_mma<<<agrid, 256>>>((float*)d_out);
}

// round 10
// speedup vs baseline: 1.5179x; 1.0400x over previous
#include <cuda_runtime.h>
#include <cuda_fp16.h>

#define BB 4
#define NN 512
#define DD 256

// ---------------- scratch (static device globals: allocation-free) ----------
__device__ __align__(16) __half g_q[BB * NN * DD];     // 1 MB
__device__ __align__(16) __half g_k[BB * NN * DD];     // 1 MB
__device__ __align__(16) float  g_wei[BB * NN * NN];   // 4 MB (raw scores)
__device__ __align__(16) __half g_weih[BB * NN * NN];  // 2 MB (softmaxed, fp16)
__device__ __align__(16) __half g_xh[BB * NN * DD];    // 1 MB (X in fp16)
__device__ __align__(16) __half g_wh[DD * DD];         // Wa_w fp16
__device__ __align__(16) __half g_uh[DD * DD];         // Ua_w fp16

// ---------------- small PTX helpers ------------------------------------------
__device__ __forceinline__ unsigned tanh_h2(unsigned xi) {
    unsigned yi;
    asm("tanh.approx.f16x2 %0, %1;" : "=r"(yi) : "r"(xi));
    return yi;
}
__device__ __forceinline__ unsigned hadd2_u(unsigned a, unsigned b) {
    unsigned c;
    asm("add.f16x2 %0, %1, %2;" : "=r"(c) : "r"(a), "r"(b));
    return c;
}
__device__ __forceinline__ unsigned smem_u32(const void* p) {
    return (unsigned)__cvta_generic_to_shared(p);
}
__device__ __forceinline__ void cp16(void* dst, const void* src) {
    asm volatile("cp.async.cg.shared.global [%0], [%1], 16;"
        :: "r"(smem_u32(dst)), "l"(src));
}
#define CP_COMMIT() asm volatile("cp.async.commit_group;")
#define CP_WAIT0()  asm volatile("cp.async.wait_group 0;")

__device__ __forceinline__ void ldsm_x4(unsigned* r, const __half* p) {
    unsigned a = smem_u32(p);
    asm volatile("ldmatrix.sync.aligned.m8n8.x4.shared.b16 {%0,%1,%2,%3}, [%4];"
        : "=r"(r[0]), "=r"(r[1]), "=r"(r[2]), "=r"(r[3]) : "r"(a));
}
__device__ __forceinline__ void ldsm_x4_trans(unsigned* r, const __half* p) {
    unsigned a = smem_u32(p);
    asm volatile("ldmatrix.sync.aligned.m8n8.x4.trans.shared.b16 {%0,%1,%2,%3}, [%4];"
        : "=r"(r[0]), "=r"(r[1]), "=r"(r[2]), "=r"(r[3]) : "r"(a));
}
__device__ __forceinline__ void mma16816(float* c, const unsigned* a,
                                         unsigned b0, unsigned b1) {
    asm volatile("mma.sync.aligned.m16n8k16.row.col.f32.f16.f16.f32 "
        "{%0,%1,%2,%3}, {%4,%5,%6,%7}, {%8,%9}, {%0,%1,%2,%3};"
        : "+f"(c[0]), "+f"(c[1]), "+f"(c[2]), "+f"(c[3])
        : "r"(a[0]), "r"(a[1]), "r"(a[2]), "r"(a[3]), "r"(b0), "r"(b1));
}

// ---------------- kernel 0: fp32 -> fp16 conversions --------------------------
// float4 units: X = 131072 f4; Wa_w = 16384 (cum 147456); Ua_w = 16384 (cum 163840)
__global__ __launch_bounds__(256) void conv_kernel(
    const float4* __restrict__ X4, const float4* __restrict__ Wa4,
    const float4* __restrict__ Ua4)
{
    int i = blockIdx.x * 256 + threadIdx.x;     // 0 .. 163839
    const float4* src;
    uint2* dst;
    int j;
    if (i < 131072)      { src = X4;  j = i;          dst = (uint2*)g_xh; }
    else if (i < 147456) { src = Wa4; j = i - 131072; dst = (uint2*)g_wh; }
    else                 { src = Ua4; j = i - 147456; dst = (uint2*)g_uh; }
    float4 v = src[j];
    __half2 h01 = __floats2half2_rn(v.x, v.y);
    __half2 h23 = __floats2half2_rn(v.z, v.w);
    uint2 o;
    o.x = *reinterpret_cast<unsigned*>(&h01);
    o.y = *reinterpret_cast<unsigned*>(&h23);
    dst[j] = o;
}

// ---------------- kernel 1: q/k projections via HMMA, cp.async pipelined -----
// out[n][e] = sum_d Xh[n][d] * Wh[e][d] + bias[e], fp16 out. BM=128 BN=64 BK=32.
__global__ __launch_bounds__(256) void proj_mma(
    const float* __restrict__ Wb, const float* __restrict__ Ub)
{
    __shared__ __half As[2][128][40];   // 80B stride (5x16B): aligned + ldsm clean
    __shared__ __half Bs[2][64][40];

    const __half* A    = g_xh;
    const __half* Bw   = blockIdx.z ? g_uh : g_wh;
    const float*  bias = blockIdx.z ? Ub : Wb;
    __half*       out  = blockIdx.z ? g_k : g_q;

    const int bn = blockIdx.x * 64;
    const int bm = blockIdx.y * 128;
    const int tid = threadIdx.x, warp = tid >> 5, lane = tid & 31;
    const int wm = warp >> 1, wn = warp & 1;   // warp tile 32x32
    const int gq = lane >> 2, tq = lane & 3;

    // per-thread stage-load coordinates (3x cp.async 16B each)
    const int ar0 = tid >> 2, aq = tid & 3;           // A rows tid>>2, tid>>2+64
    const int br  = tid >> 2, bq = tid & 3;

    float acc[2][4][4] = {};   // [tm16][tn8][4]

    // prologue: stage 0
    cp16(&As[0][ar0][aq * 8],      &A[(bm + ar0) * DD + aq * 8]);
    cp16(&As[0][ar0 + 64][aq * 8], &A[(bm + ar0 + 64) * DD + aq * 8]);
    cp16(&Bs[0][br][bq * 8],       &Bw[(bn + br) * DD + bq * 8]);
    CP_COMMIT();

    #pragma unroll
    for (int it = 0; it < 8; it++) {
        CP_WAIT0();
        __syncthreads();
        if (it < 7) {
            int nk = (it + 1) * 32, s = (it + 1) & 1;
            cp16(&As[s][ar0][aq * 8],      &A[(bm + ar0) * DD + nk + aq * 8]);
            cp16(&As[s][ar0 + 64][aq * 8], &A[(bm + ar0 + 64) * DD + nk + aq * 8]);
            cp16(&Bs[s][br][bq * 8],       &Bw[(bn + br) * DD + nk + bq * 8]);
            CP_COMMIT();
        }
        const int cur = it & 1;

        #pragma unroll
        for (int ks = 0; ks < 2; ks++) {
            int kc = ks * 16;
            unsigned a[2][4], bf[2][4];
            #pragma unroll
            for (int tm = 0; tm < 2; tm++) {
                int r = wm * 32 + tm * 16 + (lane & 15);
                int c = kc + 8 * (lane >> 4);
                ldsm_x4(a[tm], &As[cur][r][c]);
            }
            #pragma unroll
            for (int tn = 0; tn < 2; tn++) {
                int r = wn * 32 + tn * 16 + (lane & 7) + 8 * (lane >> 4);
                int c = kc + 8 * ((lane >> 3) & 1);
                ldsm_x4(bf[tn], &Bs[cur][r][c]);
            }
            #pragma unroll
            for (int tm = 0; tm < 2; tm++)
                #pragma unroll
                for (int tn8 = 0; tn8 < 4; tn8++)
                    mma16816(acc[tm][tn8], a[tm],
                             bf[tn8 >> 1][(tn8 & 1) * 2],
                             bf[tn8 >> 1][(tn8 & 1) * 2 + 1]);
        }
    }

    #pragma unroll
    for (int tm = 0; tm < 2; tm++) {
        #pragma unroll
        for (int tn8 = 0; tn8 < 4; tn8++) {
            int c = bn + wn * 32 + tn8 * 8 + 2 * tq;
            float2 bv = *(const float2*)&bias[c];
            int r0 = bm + wm * 32 + tm * 16 + gq;
            __half2 h0 = __floats2half2_rn(acc[tm][tn8][0] + bv.x,
                                           acc[tm][tn8][1] + bv.y);
            __half2 h1 = __floats2half2_rn(acc[tm][tn8][2] + bv.x,
                                           acc[tm][tn8][3] + bv.y);
            *(__half2*)&out[r0 * DD + c] = h0;
            *(__half2*)&out[(r0 + 8) * DD + c] = h1;
        }
    }
}

// ---------------- kernel 2: additive-attention scores (fp16x2 tanh) ---------
#define KT 32
#define QB 64
#define QSTAGE 32

__global__ __launch_bounds__(256, 2) void score_kernel(const float* __restrict__ Va)
{
    __shared__ __align__(16) unsigned q_sh[QSTAGE][320];

    const int tid  = threadIdx.x;
    const int w    = tid >> 5;
    const int lane = tid & 31;
    const int dg   = lane >> 2;
    const int kis  = lane & 3;

    const int b     = blockIdx.z;
    const int k0    = blockIdx.x * KT;
    const int qbase = blockIdx.y * QB;
    const int krow  = k0 + w * 4 + kis;

    unsigned kreg[16];
    {
        const uint4* kp = reinterpret_cast<const uint4*>(
            g_k + ((b * NN + krow) << 8) + dg * 32);
        #pragma unroll
        for (int j = 0; j < 4; j++) {
            uint4 t = kp[j];
            kreg[4*j+0] = t.x; kreg[4*j+1] = t.y;
            kreg[4*j+2] = t.z; kreg[4*j+3] = t.w;
        }
    }
    float vreg[32];
    {
        const float4* vp = reinterpret_cast<const float4*>(Va + dg * 32);
        #pragma unroll
        for (int j = 0; j < 8; j++) {
            float4 v = vp[j];
            vreg[4*j+0] = v.x; vreg[4*j+1] = v.y; vreg[4*j+2] = v.z; vreg[4*j+3] = v.w;
        }
    }

    for (int qc = 0; qc < QB; qc += QSTAGE) {
        __syncthreads();
        const uint4* gq4 = reinterpret_cast<const uint4*>(
            g_q + ((b * NN + qbase + qc) << 8));
        #pragma unroll
        for (int l = 0; l < 4; l++) {
            int idx = tid + 256 * l;
            int r  = idx >> 5;
            int p4 = idx & 31;
            uint4 v = gq4[(r << 5) + p4];
            *reinterpret_cast<uint4*>(&q_sh[r][(p4 >> 2) * 40 + (p4 & 3) * 4]) = v;
        }
        __syncthreads();

        #pragma unroll 2
        for (int qi = 0; qi < QSTAGE; qi++) {
            const uint4* q4 = reinterpret_cast<const uint4*>(&q_sh[qi][dg * 40]);
            float a0 = 0.f, a1 = 0.f, a2 = 0.f, a3 = 0.f;
            #pragma unroll
            for (int j = 0; j < 4; j++) {
                uint4 qv = q4[j];
                unsigned qh[4] = {qv.x, qv.y, qv.z, qv.w};
                #pragma unroll
                for (int u = 0; u < 4; u++) {
                    int i = 4 * j + u;
                    unsigned t = tanh_h2(hadd2_u(qh[u], kreg[i]));
                    __half2 th = *reinterpret_cast<__half2*>(&t);
                    float2 f = __half22float2(th);
                    if (u & 1) {
                        a2 = fmaf(vreg[2*i],   f.x, a2);
                        a3 = fmaf(vreg[2*i+1], f.y, a3);
                    } else {
                        a0 = fmaf(vreg[2*i],   f.x, a0);
                        a1 = fmaf(vreg[2*i+1], f.y, a1);
                    }
                }
            }
            float partial = (a0 + a1) + (a2 + a3);
            partial += __shfl_xor_sync(0xffffffffu, partial, 16);
            partial += __shfl_xor_sync(0xffffffffu, partial, 8);
            partial += __shfl_xor_sync(0xffffffffu, partial, 4);
            if (dg == 0) {
                g_wei[((b * NN + qbase + qc + qi) << 9) + krow] = partial;
            }
        }
    }
}

// ---------------- kernel 3: masked softmax -> fp16 weights -------------------
__global__ __launch_bounds__(128) void softmax_kernel(const int* __restrict__ mask)
{
    const int row = blockIdx.x;
    const float* wrow = g_wei + row * NN;
    const int* mrow = mask + row * NN;
    const int t = threadIdx.x;
    __shared__ float red[4];

    float4 v = reinterpret_cast<const float4*>(wrow)[t];
    int4   m = reinterpret_cast<const int4*>(mrow)[t];
    if (m.x == 0) v.x = -1e30f;
    if (m.y == 0) v.y = -1e30f;
    if (m.z == 0) v.z = -1e30f;
    if (m.w == 0) v.w = -1e30f;

    float mx = fmaxf(fmaxf(v.x, v.y), fmaxf(v.z, v.w));
    #pragma unroll
    for (int s = 16; s > 0; s >>= 1) mx = fmaxf(mx, __shfl_xor_sync(0xffffffffu, mx, s));
    if ((t & 31) == 0) red[t >> 5] = mx;
    __syncthreads();
    mx = fmaxf(fmaxf(red[0], red[1]), fmaxf(red[2], red[3]));
    __syncthreads();

    v.x = __expf(v.x - mx); v.y = __expf(v.y - mx);
    v.z = __expf(v.z - mx); v.w = __expf(v.w - mx);
    float sum = (v.x + v.y) + (v.z + v.w);
    #pragma unroll
    for (int s = 16; s > 0; s >>= 1) sum += __shfl_xor_sync(0xffffffffu, sum, s);
    if ((t & 31) == 0) red[t >> 5] = sum;
    __syncthreads();
    sum = (red[0] + red[1]) + (red[2] + red[3]);
    float inv = 1.0f / sum;

    __half2 h01 = __floats2half2_rn(v.x * inv, v.y * inv);
    __half2 h23 = __floats2half2_rn(v.z * inv, v.w * inv);
    uint2 o;
    o.x = *reinterpret_cast<unsigned*>(&h01);
    o.y = *reinterpret_cast<unsigned*>(&h23);
    reinterpret_cast<uint2*>(g_weih + row * NN)[t] = o;
}

// ---------------- kernel 4: out = wei @ X via HMMA, cp.async pipelined -------
// C[q][d] = sum_k weih[q][k] * Xh[k][d], per batch. BM=64 BN=64 BK=32.
__global__ __launch_bounds__(256) void av_mma(float* __restrict__ out)
{
    __shared__ __half As[2][64][40];
    __shared__ __half Bs[2][32][72];   // 144B stride (9x16B): aligned + trans-clean

    const int b  = blockIdx.z;
    const int bn = blockIdx.x * 64;   // d
    const int bm = blockIdx.y * 64;   // q
    const __half* A  = g_weih + b * NN * NN;
    const __half* Bx = g_xh + b * NN * DD;

    const int tid = threadIdx.x, warp = tid >> 5, lane = tid & 31;
    const int wm = warp >> 2, wn = warp & 3;   // warp tile 32x16
    const int gq = lane >> 2, tq = lane & 3;

    const int ar = tid >> 2, aq = tid & 3;    // A: 64 rows x 4 quads
    const int br = tid >> 3, bq = tid & 7;    // B: 32 rows x 8 quads

    float acc[2][2][4] = {};

    // prologue: stage 0
    cp16(&As[0][ar][aq * 8], &A[(bm + ar) * NN + aq * 8]);
    cp16(&Bs[0][br][bq * 8], &Bx[br * DD + bn + bq * 8]);
    CP_COMMIT();

    #pragma unroll 1
    for (int it = 0; it < 16; it++) {
        CP_WAIT0();
        __syncthreads();
        if (it < 15) {
            int nk = (it + 1) * 32, s = (it + 1) & 1;
            cp16(&As[s][ar][aq * 8], &A[(bm + ar) * NN + nk + aq * 8]);
            cp16(&Bs[s][br][bq * 8], &Bx[(nk + br) * DD + bn + bq * 8]);
            CP_COMMIT();
        }
        const int cur = it & 1;

        #pragma unroll
        for (int ks = 0; ks < 2; ks++) {
            int kc = ks * 16;
            unsigned a[2][4], bf[4];
            #pragma unroll
            for (int tm = 0; tm < 2; tm++) {
                int r = wm * 32 + tm * 16 + (lane & 15);
                int c = kc + 8 * (lane >> 4);
                ldsm_x4(a[tm], &As[cur][r][c]);
            }
            {
                int kr = kc + (lane & 7) + 8 * ((lane >> 3) & 1);
                int nc = wn * 16 + 8 * (lane >> 4);
                ldsm_x4_trans(bf, &Bs[cur][kr][nc]);
            }
            #pragma unroll
            for (int tm = 0; tm < 2; tm++)
                #pragma unroll
                for (int tn8 = 0; tn8 < 2; tn8++)
                    mma16816(acc[tm][tn8], a[tm], bf[tn8 * 2], bf[tn8 * 2 + 1]);
        }
    }

    #pragma unroll
    for (int tm = 0; tm < 2; tm++) {
        #pragma unroll
        for (int tn8 = 0; tn8 < 2; tn8++) {
            int c  = bn + wn * 16 + tn8 * 8 + 2 * tq;
            int r0 = bm + wm * 32 + tm * 16 + gq;
            *(float2*)&out[(b * NN + r0) * DD + c] =
                make_float2(acc[tm][tn8][0], acc[tm][tn8][1]);
            *(float2*)&out[(b * NN + r0 + 8) * DD + c] =
                make_float2(acc[tm][tn8][2], acc[tm][tn8][3]);
        }
    }
}

// ---------------- launcher ---------------------------------------------------
extern "C" void kernel_launch(void* const* d_in, const int* in_sizes, int n_in,
                              void* d_out, int out_size)
{
    const float* X    = (const float*)d_in[0];  // [4,512,256]
    const int*   mask = (const int*)  d_in[1];  // [4,512,512]
    const float* Wa_w = (const float*)d_in[2];  // [256,256]
    const float* Wa_b = (const float*)d_in[3];  // [256]
    const float* Ua_w = (const float*)d_in[4];  // [256,256]
    const float* Ua_b = (const float*)d_in[5];  // [256]
    const float* Va_w = (const float*)d_in[6];  // [1,256]
    // d_in[7] = Va_b : softmax-invariant constant -> unused

    (void)in_sizes; (void)n_in; (void)out_size;

    conv_kernel<<<640, 256>>>((const float4*)X, (const float4*)Wa_w,
                              (const float4*)Ua_w);

    dim3 pgrid(DD / 64, (BB * NN) / 128, 2);    // 4 x 16 x 2 = 128 blocks
    proj_mma<<<pgrid, 256>>>(Wa_b, Ua_b);

    dim3 sgrid(NN / KT, NN / QB, BB);           // 16 x 8 x 4 = 512 blocks
    score_kernel<<<sgrid, 256>>>(Va_w);

    softmax_kernel<<<BB * NN, 128>>>(mask);

    dim3 agrid(DD / 64, NN / 64, BB);           // 4 x 8 x 4 = 128 blocks
    av_mma<<<agrid, 256>>>((float*)d_out);
}

// round 11
// speedup vs baseline: 1.5208x; 1.0020x over previous
#include <cuda_runtime.h>
#include <cuda_fp16.h>

#define BB 4
#define NN 512
#define DD 256

// ---------------- scratch (static device globals: allocation-free) ----------
__device__ __align__(16) __half g_q[BB * NN * DD];     // 1 MB
__device__ __align__(16) __half g_k[BB * NN * DD];     // 1 MB
__device__ __align__(16) float  g_wei[BB * NN * NN];   // 4 MB (raw scores)
__device__ __align__(16) __half g_weih[BB * NN * NN];  // 2 MB (softmaxed, fp16)
__device__ __align__(16) __half g_xh[BB * NN * DD];    // 1 MB (X in fp16)
__device__ __align__(16) __half g_wh[DD * DD];         // Wa_w fp16
__device__ __align__(16) __half g_uh[DD * DD];         // Ua_w fp16

// ---------------- small PTX helpers ------------------------------------------
__device__ __forceinline__ unsigned tanh_h2(unsigned xi) {
    unsigned yi;
    asm("tanh.approx.f16x2 %0, %1;" : "=r"(yi) : "r"(xi));
    return yi;
}
__device__ __forceinline__ unsigned hadd2_u(unsigned a, unsigned b) {
    unsigned c;
    asm("add.f16x2 %0, %1, %2;" : "=r"(c) : "r"(a), "r"(b));
    return c;
}
__device__ __forceinline__ unsigned hfma2_u(unsigned a, unsigned b, unsigned c) {
    unsigned d;
    asm("fma.rn.f16x2 %0, %1, %2, %3;" : "=r"(d) : "r"(a), "r"(b), "r"(c));
    return d;
}
__device__ __forceinline__ unsigned smem_u32(const void* p) {
    return (unsigned)__cvta_generic_to_shared(p);
}
__device__ __forceinline__ void cp16(void* dst, const void* src) {
    asm volatile("cp.async.cg.shared.global [%0], [%1], 16;"
        :: "r"(smem_u32(dst)), "l"(src));
}
#define CP_COMMIT() asm volatile("cp.async.commit_group;")
#define CP_WAIT0()  asm volatile("cp.async.wait_group 0;")

__device__ __forceinline__ void ldsm_x4(unsigned* r, const __half* p) {
    unsigned a = smem_u32(p);
    asm volatile("ldmatrix.sync.aligned.m8n8.x4.shared.b16 {%0,%1,%2,%3}, [%4];"
        : "=r"(r[0]), "=r"(r[1]), "=r"(r[2]), "=r"(r[3]) : "r"(a));
}
__device__ __forceinline__ void ldsm_x4_trans(unsigned* r, const __half* p) {
    unsigned a = smem_u32(p);
    asm volatile("ldmatrix.sync.aligned.m8n8.x4.trans.shared.b16 {%0,%1,%2,%3}, [%4];"
        : "=r"(r[0]), "=r"(r[1]), "=r"(r[2]), "=r"(r[3]) : "r"(a));
}
__device__ __forceinline__ void mma16816(float* c, const unsigned* a,
                                         unsigned b0, unsigned b1) {
    asm volatile("mma.sync.aligned.m16n8k16.row.col.f32.f16.f16.f32 "
        "{%0,%1,%2,%3}, {%4,%5,%6,%7}, {%8,%9}, {%0,%1,%2,%3};"
        : "+f"(c[0]), "+f"(c[1]), "+f"(c[2]), "+f"(c[3])
        : "r"(a[0]), "r"(a[1]), "r"(a[2]), "r"(a[3]), "r"(b0), "r"(b1));
}

// ---------------- kernel 0: fp32 -> fp16 conversions --------------------------
// float4 units: X = 131072 f4; Wa_w = 16384 (cum 147456); Ua_w = 16384 (cum 163840)
__global__ __launch_bounds__(256) void conv_kernel(
    const float4* __restrict__ X4, const float4* __restrict__ Wa4,
    const float4* __restrict__ Ua4)
{
    int i = blockIdx.x * 256 + threadIdx.x;     // 0 .. 163839
    const float4* src;
    uint2* dst;
    int j;
    if (i < 131072)      { src = X4;  j = i;          dst = (uint2*)g_xh; }
    else if (i < 147456) { src = Wa4; j = i - 131072; dst = (uint2*)g_wh; }
    else                 { src = Ua4; j = i - 147456; dst = (uint2*)g_uh; }
    float4 v = src[j];
    __half2 h01 = __floats2half2_rn(v.x, v.y);
    __half2 h23 = __floats2half2_rn(v.z, v.w);
    uint2 o;
    o.x = *reinterpret_cast<unsigned*>(&h01);
    o.y = *reinterpret_cast<unsigned*>(&h23);
    dst[j] = o;
}

// ---------------- kernel 1: q/k projections via HMMA, cp.async pipelined -----
__global__ __launch_bounds__(256) void proj_mma(
    const float* __restrict__ Wb, const float* __restrict__ Ub)
{
    __shared__ __half As[2][128][40];
    __shared__ __half Bs[2][64][40];

    const __half* A    = g_xh;
    const __half* Bw   = blockIdx.z ? g_uh : g_wh;
    const float*  bias = blockIdx.z ? Ub : Wb;
    __half*       out  = blockIdx.z ? g_k : g_q;

    const int bn = blockIdx.x * 64;
    const int bm = blockIdx.y * 128;
    const int tid = threadIdx.x, warp = tid >> 5, lane = tid & 31;
    const int wm = warp >> 1, wn = warp & 1;
    const int gq = lane >> 2, tq = lane & 3;

    const int ar0 = tid >> 2, aq = tid & 3;
    const int br  = tid >> 2, bq = tid & 3;

    float acc[2][4][4] = {};

    cp16(&As[0][ar0][aq * 8],      &A[(bm + ar0) * DD + aq * 8]);
    cp16(&As[0][ar0 + 64][aq * 8], &A[(bm + ar0 + 64) * DD + aq * 8]);
    cp16(&Bs[0][br][bq * 8],       &Bw[(bn + br) * DD + bq * 8]);
    CP_COMMIT();

    #pragma unroll
    for (int it = 0; it < 8; it++) {
        CP_WAIT0();
        __syncthreads();
        if (it < 7) {
            int nk = (it + 1) * 32, s = (it + 1) & 1;
            cp16(&As[s][ar0][aq * 8],      &A[(bm + ar0) * DD + nk + aq * 8]);
            cp16(&As[s][ar0 + 64][aq * 8], &A[(bm + ar0 + 64) * DD + nk + aq * 8]);
            cp16(&Bs[s][br][bq * 8],       &Bw[(bn + br) * DD + nk + bq * 8]);
            CP_COMMIT();
        }
        const int cur = it & 1;

        #pragma unroll
        for (int ks = 0; ks < 2; ks++) {
            int kc = ks * 16;
            unsigned a[2][4], bf[2][4];
            #pragma unroll
            for (int tm = 0; tm < 2; tm++) {
                int r = wm * 32 + tm * 16 + (lane & 15);
                int c = kc + 8 * (lane >> 4);
                ldsm_x4(a[tm], &As[cur][r][c]);
            }
            #pragma unroll
            for (int tn = 0; tn < 2; tn++) {
                int r = wn * 32 + tn * 16 + (lane & 7) + 8 * (lane >> 4);
                int c = kc + 8 * ((lane >> 3) & 1);
                ldsm_x4(bf[tn], &Bs[cur][r][c]);
            }
            #pragma unroll
            for (int tm = 0; tm < 2; tm++)
                #pragma unroll
                for (int tn8 = 0; tn8 < 4; tn8++)
                    mma16816(acc[tm][tn8], a[tm],
                             bf[tn8 >> 1][(tn8 & 1) * 2],
                             bf[tn8 >> 1][(tn8 & 1) * 2 + 1]);
        }
    }

    #pragma unroll
    for (int tm = 0; tm < 2; tm++) {
        #pragma unroll
        for (int tn8 = 0; tn8 < 4; tn8++) {
            int c = bn + wn * 32 + tn8 * 8 + 2 * tq;
            float2 bv = *(const float2*)&bias[c];
            int r0 = bm + wm * 32 + tm * 16 + gq;
            __half2 h0 = __floats2half2_rn(acc[tm][tn8][0] + bv.x,
                                           acc[tm][tn8][1] + bv.y);
            __half2 h1 = __floats2half2_rn(acc[tm][tn8][2] + bv.x,
                                           acc[tm][tn8][3] + bv.y);
            *(__half2*)&out[r0 * DD + c] = h0;
            *(__half2*)&out[(r0 + 8) * DD + c] = h1;
        }
    }
}

// ---------------- kernel 2: additive-attention scores -------------------------
// wei[b,q,k] = sum_d Va[d] * tanh(q[b,q,d] + k[b,k,d])
// Inner loop slimmed: HFMA2 fp16 accumulation (4 accumulators x 4 products),
// single fp32 conversion per qi. Va pre-packed to half2.
#define KT 32
#define QB 64
#define QSTAGE 32

__global__ __launch_bounds__(256, 2) void score_kernel(const float* __restrict__ Va)
{
    __shared__ __align__(16) unsigned q_sh[QSTAGE][320];

    const int tid  = threadIdx.x;
    const int w    = tid >> 5;
    const int lane = tid & 31;
    const int dg   = lane >> 2;
    const int kis  = lane & 3;

    const int b     = blockIdx.z;
    const int k0    = blockIdx.x * KT;
    const int qbase = blockIdx.y * QB;
    const int krow  = k0 + w * 4 + kis;

    unsigned kreg[16];
    {
        const uint4* kp = reinterpret_cast<const uint4*>(
            g_k + ((b * NN + krow) << 8) + dg * 32);
        #pragma unroll
        for (int j = 0; j < 4; j++) {
            uint4 t = kp[j];
            kreg[4*j+0] = t.x; kreg[4*j+1] = t.y;
            kreg[4*j+2] = t.z; kreg[4*j+3] = t.w;
        }
    }
    // Va chunk packed to half2 (products accumulate in fp16, short chains)
    unsigned vh[16];
    {
        const float4* vp = reinterpret_cast<const float4*>(Va + dg * 32);
        #pragma unroll
        for (int j = 0; j < 8; j++) {
            float4 v = vp[j];
            __half2 a = __floats2half2_rn(v.x, v.y);
            __half2 c = __floats2half2_rn(v.z, v.w);
            vh[2*j]   = *reinterpret_cast<unsigned*>(&a);
            vh[2*j+1] = *reinterpret_cast<unsigned*>(&c);
        }
    }

    for (int qc = 0; qc < QB; qc += QSTAGE) {
        __syncthreads();
        const uint4* gq4 = reinterpret_cast<const uint4*>(
            g_q + ((b * NN + qbase + qc) << 8));
        #pragma unroll
        for (int l = 0; l < 4; l++) {
            int idx = tid + 256 * l;
            int r  = idx >> 5;
            int p4 = idx & 31;
            uint4 v = gq4[(r << 5) + p4];
            *reinterpret_cast<uint4*>(&q_sh[r][(p4 >> 2) * 40 + (p4 & 3) * 4]) = v;
        }
        __syncthreads();

        #pragma unroll 2
        for (int qi = 0; qi < QSTAGE; qi++) {
            const uint4* q4 = reinterpret_cast<const uint4*>(&q_sh[qi][dg * 40]);
            unsigned hacc[4] = {0u, 0u, 0u, 0u};   // half2 zeros
            #pragma unroll
            for (int j = 0; j < 4; j++) {
                uint4 qv = q4[j];
                unsigned qh[4] = {qv.x, qv.y, qv.z, qv.w};
                #pragma unroll
                for (int u = 0; u < 4; u++) {
                    int i = 4 * j + u;
                    unsigned t = tanh_h2(hadd2_u(qh[u], kreg[i]));
                    hacc[u] = hfma2_u(t, vh[i], hacc[u]);   // 4 products/chain
                }
            }
            float2 f0 = __half22float2(*reinterpret_cast<__half2*>(&hacc[0]));
            float2 f1 = __half22float2(*reinterpret_cast<__half2*>(&hacc[1]));
            float2 f2 = __half22float2(*reinterpret_cast<__half2*>(&hacc[2]));
            float2 f3 = __half22float2(*reinterpret_cast<__half2*>(&hacc[3]));
            float partial = ((f0.x + f0.y) + (f1.x + f1.y))
                          + ((f2.x + f2.y) + (f3.x + f3.y));
            partial += __shfl_xor_sync(0xffffffffu, partial, 16);
            partial += __shfl_xor_sync(0xffffffffu, partial, 8);
            partial += __shfl_xor_sync(0xffffffffu, partial, 4);
            if (dg == 0) {
                g_wei[((b * NN + qbase + qc + qi) << 9) + krow] = partial;
            }
        }
    }
}

// ---------------- kernel 3: masked softmax -> fp16 weights -------------------
__global__ __launch_bounds__(128) void softmax_kernel(const int* __restrict__ mask)
{
    const int row = blockIdx.x;
    const float* wrow = g_wei + row * NN;
    const int* mrow = mask + row * NN;
    const int t = threadIdx.x;
    __shared__ float red[4];

    float4 v = reinterpret_cast<const float4*>(wrow)[t];
    int4   m = reinterpret_cast<const int4*>(mrow)[t];
    if (m.x == 0) v.x = -1e30f;
    if (m.y == 0) v.y = -1e30f;
    if (m.z == 0) v.z = -1e30f;
    if (m.w == 0) v.w = -1e30f;

    float mx = fmaxf(fmaxf(v.x, v.y), fmaxf(v.z, v.w));
    #pragma unroll
    for (int s = 16; s > 0; s >>= 1) mx = fmaxf(mx, __shfl_xor_sync(0xffffffffu, mx, s));
    if ((t & 31) == 0) red[t >> 5] = mx;
    __syncthreads();
    mx = fmaxf(fmaxf(red[0], red[1]), fmaxf(red[2], red[3]));
    __syncthreads();

    v.x = __expf(v.x - mx); v.y = __expf(v.y - mx);
    v.z = __expf(v.z - mx); v.w = __expf(v.w - mx);
    float sum = (v.x + v.y) + (v.z + v.w);
    #pragma unroll
    for (int s = 16; s > 0; s >>= 1) sum += __shfl_xor_sync(0xffffffffu, sum, s);
    if ((t & 31) == 0) red[t >> 5] = sum;
    __syncthreads();
    sum = (red[0] + red[1]) + (red[2] + red[3]);
    float inv = 1.0f / sum;

    __half2 h01 = __floats2half2_rn(v.x * inv, v.y * inv);
    __half2 h23 = __floats2half2_rn(v.z * inv, v.w * inv);
    uint2 o;
    o.x = *reinterpret_cast<unsigned*>(&h01);
    o.y = *reinterpret_cast<unsigned*>(&h23);
    reinterpret_cast<uint2*>(g_weih + row * NN)[t] = o;
}

// ---------------- kernel 4: out = wei @ X via HMMA, cp.async pipelined -------
__global__ __launch_bounds__(256) void av_mma(float* __restrict__ out)
{
    __shared__ __half As[2][64][40];
    __shared__ __half Bs[2][32][72];

    const int b  = blockIdx.z;
    const int bn = blockIdx.x * 64;
    const int bm = blockIdx.y * 64;
    const __half* A  = g_weih + b * NN * NN;
    const __half* Bx = g_xh + b * NN * DD;

    const int tid = threadIdx.x, warp = tid >> 5, lane = tid & 31;
    const int wm = warp >> 2, wn = warp & 3;
    const int gq = lane >> 2, tq = lane & 3;

    const int ar = tid >> 2, aq = tid & 3;
    const int br = tid >> 3, bq = tid & 7;

    float acc[2][2][4] = {};

    cp16(&As[0][ar][aq * 8], &A[(bm + ar) * NN + aq * 8]);
    cp16(&Bs[0][br][bq * 8], &Bx[br * DD + bn + bq * 8]);
    CP_COMMIT();

    #pragma unroll 1
    for (int it = 0; it < 16; it++) {
        CP_WAIT0();
        __syncthreads();
        if (it < 15) {
            int nk = (it + 1) * 32, s = (it + 1) & 1;
            cp16(&As[s][ar][aq * 8], &A[(bm + ar) * NN + nk + aq * 8]);
            cp16(&Bs[s][br][bq * 8], &Bx[(nk + br) * DD + bn + bq * 8]);
            CP_COMMIT();
        }
        const int cur = it & 1;

        #pragma unroll
        for (int ks = 0; ks < 2; ks++) {
            int kc = ks * 16;
            unsigned a[2][4], bf[4];
            #pragma unroll
            for (int tm = 0; tm < 2; tm++) {
                int r = wm * 32 + tm * 16 + (lane & 15);
                int c = kc + 8 * (lane >> 4);
                ldsm_x4(a[tm], &As[cur][r][c]);
            }
            {
                int kr = kc + (lane & 7) + 8 * ((lane >> 3) & 1);
                int nc = wn * 16 + 8 * (lane >> 4);
                ldsm_x4_trans(bf, &Bs[cur][kr][nc]);
            }
            #pragma unroll
            for (int tm = 0; tm < 2; tm++)
                #pragma unroll
                for (int tn8 = 0; tn8 < 2; tn8++)
                    mma16816(acc[tm][tn8], a[tm], bf[tn8 * 2], bf[tn8 * 2 + 1]);
        }
    }

    #pragma unroll
    for (int tm = 0; tm < 2; tm++) {
        #pragma unroll
        for (int tn8 = 0; tn8 < 2; tn8++) {
            int c  = bn + wn * 16 + tn8 * 8 + 2 * tq;
            int r0 = bm + wm * 32 + tm * 16 + gq;
            *(float2*)&out[(b * NN + r0) * DD + c] =
                make_float2(acc[tm][tn8][0], acc[tm][tn8][1]);
            *(float2*)&out[(b * NN + r0 + 8) * DD + c] =
                make_float2(acc[tm][tn8][2], acc[tm][tn8][3]);
        }
    }
}

// ---------------- launcher ---------------------------------------------------
extern "C" void kernel_launch(void* const* d_in, const int* in_sizes, int n_in,
                              void* d_out, int out_size)
{
    const float* X    = (const float*)d_in[0];  // [4,512,256]
    const int*   mask = (const int*)  d_in[1];  // [4,512,512]
    const float* Wa_w = (const float*)d_in[2];  // [256,256]
    const float* Wa_b = (const float*)d_in[3];  // [256]
    const float* Ua_w = (const float*)d_in[4];  // [256,256]
    const float* Ua_b = (const float*)d_in[5];  // [256]
    const float* Va_w = (const float*)d_in[6];  // [1,256]
    // d_in[7] = Va_b : softmax-invariant constant -> unused

    (void)in_sizes; (void)n_in; (void)out_size;

    conv_kernel<<<640, 256>>>((const float4*)X, (const float4*)Wa_w,
                              (const float4*)Ua_w);

    dim3 pgrid(DD / 64, (BB * NN) / 128, 2);    // 128 blocks
    proj_mma<<<pgrid, 256>>>(Wa_b, Ua_b);

    dim3 sgrid(NN / KT, NN / QB, BB);           // 512 blocks
    score_kernel<<<sgrid, 256>>>(Va_w);

    softmax_kernel<<<BB * NN, 128>>>(mask);

    dim3 agrid(DD / 64, NN / 64, BB);           // 128 blocks
    av_mma<<<agrid, 256>>>((float*)d_out);
}